// round 9
// baseline (speedup 1.0000x reference)
#include <cuda_runtime.h>

#define NT   128    // B*T
#define BB   16
#define TT   8
#define CC   512
#define C8   64
#define HW4  196    // 784/4

// Scratch (no device allocation -> __device__ globals; zero-initialized)
__device__ float g_xv[NT * CC];
__device__ float g_left[NT * C8];
__device__ float g_right[NT * C8];
__device__ float g_state[NT * C8];
__device__ int   g_cnt_nt[NT];     // self-resetting last-finisher counters
__device__ int   g_cnt_b[BB];

// ---------------------------------------------------------------------------
// Kernel 1 (fused): pool + per-nt gemm/BN/ReLU + per-batch scan.
//  - Every block pools 4 rows (one nt each, 128 blocks per nt). NO waits.
//  - The 128th finisher of an nt computes that nt's two 64-wide dots.
//  - The 8th nt-finisher of a batch runs the 8-step register scan (warp 0).
//  - Counters self-reset (last finisher stores 0) -> replay-deterministic.
// ---------------------------------------------------------------------------
__global__ void __launch_bounds__(256) pre_k(
    const float* __restrict__ x,
    const float* __restrict__ w1,
    const float* __restrict__ bn1g, const float* __restrict__ bn1b,
    const float* __restrict__ bn1m, const float* __restrict__ bn1v,
    const float* __restrict__ w2,
    const float* __restrict__ bn2g, const float* __restrict__ bn2b,
    const float* __restrict__ bn2m, const float* __restrict__ bn2v,
    const float* __restrict__ gamma_w, const float* __restrict__ gamma_b)
{
    __shared__ float  s_part[4][2];
    __shared__ float4 s_xv4[CC / 4];
    __shared__ int    s_nt, s_b;

    int tid = threadIdx.x;
    int sub = tid >> 6, i = tid & 63;
    int row = blockIdx.x * 4 + sub;          // 4 rows, all same nt
    const float4* xi = reinterpret_cast<const float4*>(x) + (size_t)row * HW4;

    // ---- pool ----
    float4 v0 = xi[i];
    float4 v1 = xi[i + 64];
    float4 v2 = xi[i + 128];
    float s = 0.f;
    if (i < 4) { float4 tv = xi[i + 192]; s = (tv.x + tv.y) + (tv.z + tv.w); }
    s += (v0.x + v0.y) + (v0.z + v0.w);
    s += (v1.x + v1.y) + (v1.z + v1.w);
    s += (v2.x + v2.y) + (v2.z + v2.w);
    #pragma unroll
    for (int o = 16; o; o >>= 1) s += __shfl_xor_sync(0xffffffffu, s, o);
    if ((i & 31) == 0) s_part[sub][i >> 5] = s;
    __syncthreads();
    if (i == 0)
        g_xv[row] = (s_part[sub][0] + s_part[sub][1]) * (1.0f / 784.0f);
    __threadfence();                          // release g_xv
    __syncthreads();

    // ---- per-nt last-finisher: gemm + BN + ReLU ----
    int nt = blockIdx.x >> 7;                 // 128 blocks per nt
    if (tid == 0) {
        int old = atomicAdd(&g_cnt_nt[nt], 1);
        if (old == 127) { g_cnt_nt[nt] = 0; s_nt = nt; } else s_nt = -1;
    }
    __syncthreads();
    if (s_nt < 0) return;

    __threadfence();                          // acquire g_xv
    if (tid < CC / 4)
        s_xv4[tid] = *(reinterpret_cast<const float4*>(g_xv) + nt * (CC / 4) + tid);
    __syncthreads();

    if (tid < 128) {
        int half = tid >> 6, ch = tid & 63;
        const float* wsel = half ? w2   : w1;
        const float* gsel = half ? bn2g : bn1g;
        const float* bsel = half ? bn2b : bn1b;
        const float* msel = half ? bn2m : bn1m;
        const float* vsel = half ? bn2v : bn1v;
        const float4* wr = reinterpret_cast<const float4*>(wsel) + ch * (CC / 4);
        float a0 = 0.f, a1 = 0.f, a2 = 0.f, a3 = 0.f;
        #pragma unroll 8
        for (int k = 0; k < CC / 4; k++) {
            float4 wv = __ldg(wr + k);
            float4 xv = s_xv4[k];
            a0 += xv.x * wv.x;
            a1 += xv.y * wv.y;
            a2 += xv.z * wv.z;
            a3 += xv.w * wv.w;
        }
        float acc = (a0 + a1) + (a2 + a3);
        float sc  = __ldg(gsel + ch) * rsqrtf(__ldg(vsel + ch) + 1e-5f);
        float val = fmaxf((acc - __ldg(msel + ch)) * sc + __ldg(bsel + ch), 0.f);
        if (half == 0) g_left [nt * C8 + ch] = val;
        else           g_right[nt * C8 + ch] = val;
    }
    __threadfence();                          // release g_left/g_right
    __syncthreads();

    // ---- per-batch last-finisher: register-resident scan (warp 0) ----
    int b = nt >> 3;
    if (tid == 0) {
        int old = atomicAdd(&g_cnt_b[b], 1);
        if (old == TT - 1) { g_cnt_b[b] = 0; s_b = b; } else s_b = -1;
    }
    __syncthreads();
    if (s_b < 0 || tid >= 32) return;

    __threadfence();                          // acquire g_left/g_right
    int bb = s_b, lane = tid;
    float L0[7], L1[7], R0[7], R1[7];
    #pragma unroll
    for (int t = 0; t < 7; t++) {
        L0[t] = g_left [(bb * TT + t)     * C8 + lane];
        L1[t] = g_left [(bb * TT + t)     * C8 + lane + 32];
        R0[t] = g_right[(bb * TT + t + 1) * C8 + lane];
        R1[t] = g_right[(bb * TT + t + 1) * C8 + lane + 32];
    }
    float gm0 = __ldg(gamma_w + lane);
    float gm1 = __ldg(gamma_w + lane + 32);
    float gm2 = __ldg(gamma_w + lane + 64);
    float gm3 = __ldg(gamma_w + lane + 96);
    float gb  = __ldg(gamma_b);

    float s0 = 1.f, s1 = 1.f;
    #pragma unroll
    for (int t = 0; t < TT; t++) {
        float d0 = (t < TT - 1) ? (L0[t] - R0[t]) : 1.f;
        float d1 = (t < TT - 1) ? (L1[t] - R1[t]) : 1.f;
        float acc = d0 * gm0 + d1 * gm1 + s0 * gm2 + s1 * gm3;
        #pragma unroll
        for (int o = 16; o; o >>= 1) acc += __shfl_xor_sync(0xffffffffu, acc, o);
        float g = 1.0f / (1.0f + __expf(-(acc + gb)));
        s0 = d0 * g + s0 * (1.0f - g);
        s1 = d1 * g + s1 * (1.0f - g);
        g_state[(bb * TT + t) * C8 + lane]      = s0;
        g_state[(bb * TT + t) * C8 + lane + 32] = s1;
    }
}

// ---------------------------------------------------------------------------
// Kernel 2: fused attention + scale, REVERSED block order for L2 reuse of
// the x tail that pool left resident. Streaming stores.
// ---------------------------------------------------------------------------
__global__ void scale_att_k(const float* __restrict__ x,
                            const float* __restrict__ Wa_w,
                            const float* __restrict__ Wa_b,
                            float* __restrict__ out) {
    __shared__ float s_part[4][2];
    int tid  = threadIdx.x;
    int sub  = tid >> 6, i = tid & 63;
    int rb   = gridDim.x - 1 - blockIdx.x;   // reversed
    int row  = rb * 4 + sub;                 // (nt*CC + c) row id
    int nt   = row >> 9;
    int c    = row & (CC - 1);

    const float4* xi = reinterpret_cast<const float4*>(x)   + (size_t)row * HW4;
    float4*       xo = reinterpret_cast<float4*>(out)       + (size_t)row * HW4;

    float4 v0 = __ldg(xi + i);
    float4 v1 = __ldg(xi + i + 64);
    float4 v2 = __ldg(xi + i + 128);
    float4 v3;
    bool tail = (i < 4);
    if (tail) v3 = __ldg(xi + i + 192);

    float p = g_state[nt * C8 + i] * __ldg(Wa_w + c * C8 + i);
    #pragma unroll
    for (int o = 16; o; o >>= 1) p += __shfl_xor_sync(0xffffffffu, p, o);
    if ((i & 31) == 0) s_part[sub][i >> 5] = p;
    __syncthreads();
    float a = s_part[sub][0] + s_part[sub][1] + __ldg(Wa_b + c);
    float s = 1.0f / (1.0f + __expf(-a));

    v0.x *= s; v0.y *= s; v0.z *= s; v0.w *= s;
    v1.x *= s; v1.y *= s; v1.z *= s; v1.w *= s;
    v2.x *= s; v2.y *= s; v2.z *= s; v2.w *= s;
    __stcs(xo + i,       v0);
    __stcs(xo + i + 64,  v1);
    __stcs(xo + i + 128, v2);
    if (tail) {
        v3.x *= s; v3.y *= s; v3.z *= s; v3.w *= s;
        __stcs(xo + i + 192, v3);
    }
}

// ---------------------------------------------------------------------------
extern "C" void kernel_launch(void* const* d_in, const int* in_sizes, int n_in,
                              void* d_out, int out_size) {
    const float* x       = (const float*)d_in[0];
    const float* w1      = (const float*)d_in[1];
    const float* bn1_g   = (const float*)d_in[2];
    const float* bn1_b   = (const float*)d_in[3];
    const float* bn1_m   = (const float*)d_in[4];
    const float* bn1_v   = (const float*)d_in[5];
    const float* w2      = (const float*)d_in[6];
    const float* bn2_g   = (const float*)d_in[7];
    const float* bn2_b   = (const float*)d_in[8];
    const float* bn2_m   = (const float*)d_in[9];
    const float* bn2_v   = (const float*)d_in[10];
    const float* Wa_w    = (const float*)d_in[11];
    const float* Wa_b    = (const float*)d_in[12];
    const float* gamma_w = (const float*)d_in[13];
    const float* gamma_b = (const float*)d_in[14];
    float* out = (float*)d_out;

    pre_k<<<(NT * CC) / 4, 256>>>(x,
                                  w1, bn1_g, bn1_b, bn1_m, bn1_v,
                                  w2, bn2_g, bn2_b, bn2_m, bn2_v,
                                  gamma_w, gamma_b);
    scale_att_k<<<(NT * CC) / 4, 256>>>(x, Wa_w, Wa_b, out);
}